// round 1
// baseline (speedup 1.0000x reference)
#include <cuda_runtime.h>
#include <math.h>
#include <stdint.h>

// Problem constants
#define Bc   32
#define Lc   1024
#define Dc   512
#define Hc   8
#define DHc  64
#define DFFc 2048
#define NLc  6
#define Ac   21
#define Mrows (Bc*Lc)   // 32768

// ---------------- scratch (device globals; no runtime allocation) ----------------
__device__ float g_h[(size_t)Mrows * Dc];   // residual stream
__device__ float g_n[(size_t)Mrows * Dc];   // LN output / attention output (reused)
__device__ float g_q[(size_t)Mrows * Dc];
__device__ float g_k[(size_t)Mrows * Dc];
__device__ float g_v[(size_t)Mrows * Dc];
__device__ float g_f[(size_t)Mrows * DFFc]; // FFN intermediate

// ---------------- embedding: h = tok_emb[x] + pos_emb ----------------
__global__ void embed_k(const int* __restrict__ x, const float* __restrict__ tok,
                        const float* __restrict__ pos, float* __restrict__ h) {
    size_t i = (size_t)blockIdx.x * blockDim.x + threadIdx.x;   // over float4s
    const size_t total = (size_t)Mrows * (Dc / 4);
    if (i >= total) return;
    size_t row = i / (Dc / 4);
    int c4 = (int)(i % (Dc / 4));
    int tid = x[row];
    int l = (int)(row & (Lc - 1));
    float4 a = ((const float4*)tok)[(size_t)tid * (Dc / 4) + c4];
    float4 p = ((const float4*)pos)[(size_t)l * (Dc / 4) + c4];
    float4 o; o.x = a.x + p.x; o.y = a.y + p.y; o.z = a.z + p.z; o.w = a.w + p.w;
    ((float4*)h)[i] = o;
}

// ---------------- layernorm: warp per row, exact two-pass variance ----------------
__global__ void ln_k(const float* __restrict__ X, const float* __restrict__ gs,
                     const float* __restrict__ gb, float* __restrict__ Y) {
    int w = (int)((blockIdx.x * blockDim.x + threadIdx.x) >> 5);
    int lane = threadIdx.x & 31;
    if (w >= Mrows) return;
    const float* x = X + (size_t)w * Dc;
    float4 v[4];
    float s = 0.f;
#pragma unroll
    for (int t = 0; t < 4; t++) {
        v[t] = ((const float4*)x)[lane + 32 * t];
        s += v[t].x + v[t].y + v[t].z + v[t].w;
    }
#pragma unroll
    for (int o = 16; o; o >>= 1) s += __shfl_xor_sync(0xffffffffu, s, o);
    float mu = s * (1.0f / Dc);
    float ss = 0.f;
#pragma unroll
    for (int t = 0; t < 4; t++) {
        float dx = v[t].x - mu, dy = v[t].y - mu, dz = v[t].z - mu, dw = v[t].w - mu;
        ss += dx * dx + dy * dy + dz * dz + dw * dw;
    }
#pragma unroll
    for (int o = 16; o; o >>= 1) ss += __shfl_xor_sync(0xffffffffu, ss, o);
    float var = ss * (1.0f / Dc);
    float rs = rsqrtf(var + 1e-6f);
    float* y = Y + (size_t)w * Dc;
#pragma unroll
    for (int t = 0; t < 4; t++) {
        int f4 = lane + 32 * t;
        float4 g4 = ((const float4*)gs)[f4];
        float4 b4 = ((const float4*)gb)[f4];
        float4 o;
        o.x = (v[t].x - mu) * rs * g4.x + b4.x;
        o.y = (v[t].y - mu) * rs * g4.y + b4.y;
        o.z = (v[t].z - mu) * rs * g4.z + b4.z;
        o.w = (v[t].w - mu) * rs * g4.w + b4.w;
        ((float4*)y)[f4] = o;
    }
}

// ---------------- SGEMM: C[M,N] = A[M,K] @ W[K,N] + bias (+resid / gelu) ----------
// MODE 0: +bias; MODE 1: gelu(+bias); MODE 2: +bias +resid
__device__ __forceinline__ float gelu_tanh(float x) {
    float x3 = x * x * x;
    return 0.5f * x * (1.0f + tanhf(0.7978845608028654f * (x + 0.044715f * x3)));
}

template <int MODE>
__global__ void __launch_bounds__(256) gemm_k(
    const float* __restrict__ A, const float* __restrict__ W,
    const float* __restrict__ bias, const float* __restrict__ R,
    float* __restrict__ C, int M, int N, int K) {
    __shared__ float As[16][128];
    __shared__ float Bs[16][128];

    const int tid = threadIdx.x;
    const int tx = tid & 15;
    const int ty = tid >> 4;
    const size_t mBase = (size_t)blockIdx.y * 128;
    const int nBase = blockIdx.x * 128;

    float acc[8][8];
#pragma unroll
    for (int i = 0; i < 8; i++)
#pragma unroll
        for (int j = 0; j < 8; j++) acc[i][j] = 0.f;

    for (int k0 = 0; k0 < K; k0 += 16) {
#pragma unroll
        for (int u = 0; u < 2; u++) {
            int idx = tid + u * 256;
            // A tile: 128 rows x 4 float4 along K (coalesced global read)
            int ar = idx >> 2;
            int ak = (idx & 3) * 4;
            float4 av = *(const float4*)(A + (mBase + ar) * (size_t)K + k0 + ak);
            As[ak + 0][ar] = av.x;
            As[ak + 1][ar] = av.y;
            As[ak + 2][ar] = av.z;
            As[ak + 3][ar] = av.w;
            // B tile: 16 rows x 32 float4 along N (coalesced)
            int br = idx >> 5;
            int bc = (idx & 31) * 4;
            *(float4*)&Bs[br][bc] =
                *(const float4*)(W + (size_t)(k0 + br) * N + nBase + bc);
        }
        __syncthreads();
#pragma unroll
        for (int kk = 0; kk < 16; kk++) {
            float4 a0 = *(const float4*)&As[kk][ty * 4];
            float4 a1 = *(const float4*)&As[kk][64 + ty * 4];
            float4 b0 = *(const float4*)&Bs[kk][tx * 4];
            float4 b1 = *(const float4*)&Bs[kk][64 + tx * 4];
            float ra[8] = {a0.x, a0.y, a0.z, a0.w, a1.x, a1.y, a1.z, a1.w};
            float rb[8] = {b0.x, b0.y, b0.z, b0.w, b1.x, b1.y, b1.z, b1.w};
#pragma unroll
            for (int i = 0; i < 8; i++)
#pragma unroll
                for (int j = 0; j < 8; j++) acc[i][j] += ra[i] * rb[j];
        }
        __syncthreads();
    }

#pragma unroll
    for (int i = 0; i < 8; i++) {
        int rloc = (i < 4) ? (ty * 4 + i) : (64 + ty * 4 + (i - 4));
        size_t row = mBase + rloc;
#pragma unroll
        for (int jg = 0; jg < 2; jg++) {
            int c = nBase + jg * 64 + tx * 4;
            float4 bv = *(const float4*)(bias + c);
            float4 o;
            o.x = acc[i][jg * 4 + 0] + bv.x;
            o.y = acc[i][jg * 4 + 1] + bv.y;
            o.z = acc[i][jg * 4 + 2] + bv.z;
            o.w = acc[i][jg * 4 + 3] + bv.w;
            if (MODE == 1) {
                o.x = gelu_tanh(o.x); o.y = gelu_tanh(o.y);
                o.z = gelu_tanh(o.z); o.w = gelu_tanh(o.w);
            }
            if (MODE == 2) {
                float4 rv = *(const float4*)(R + row * (size_t)N + c);
                o.x += rv.x; o.y += rv.y; o.z += rv.z; o.w += rv.w;
            }
            *(float4*)(C + row * (size_t)N + c) = o;
        }
    }
}

// ---------------- junction-tree attention: warp per (b,l,h), <=8 keys ----------
__global__ void attn_k(const float* __restrict__ Q, const float* __restrict__ K,
                       const float* __restrict__ V, float* __restrict__ O) {
    int gw = (int)((blockIdx.x * blockDim.x + threadIdx.x) >> 5);  // = bl*H + h
    int lane = threadIdx.x & 31;
    int h = gw & (Hc - 1);
    int bl = gw >> 3;
    int l = bl & (Lc - 1);
    int c = l >> 2, r = l & 3;

    int keys[8];
    int nk = 0;
    if (c > 0) {
        int p = (c - 1) << 2;
        keys[0] = p; keys[1] = p + 1; keys[2] = p + 2; keys[3] = p + 3;
        nk = 4;
    }
    int ob = c << 2;
#pragma unroll
    for (int t = 0; t < 4; t++)
        if (t <= r) keys[nk++] = ob + t;

    int blBase = bl - l;  // b*L
    size_t qoff = (size_t)bl * Dc + h * DHc;
    float q0 = Q[qoff + lane];
    float q1 = Q[qoff + lane + 32];

    float s[8];
    for (int j = 0; j < nk; j++) {
        size_t ko = (size_t)(blBase + keys[j]) * Dc + h * DHc;
        float d = q0 * K[ko + lane] + q1 * K[ko + lane + 32];
#pragma unroll
        for (int o = 16; o; o >>= 1) d += __shfl_xor_sync(0xffffffffu, d, o);
        s[j] = d * 0.125f;  // 1/sqrt(64)
    }
    float mx = s[0];
    for (int j = 1; j < nk; j++) mx = fmaxf(mx, s[j]);
    float sum = 0.f;
    for (int j = 0; j < nk; j++) { s[j] = expf(s[j] - mx); sum += s[j]; }
    float inv = 1.0f / sum;
    float o0 = 0.f, o1 = 0.f;
    for (int j = 0; j < nk; j++) {
        size_t vo = (size_t)(blBase + keys[j]) * Dc + h * DHc;
        o0 += s[j] * V[vo + lane];
        o1 += s[j] * V[vo + lane + 32];
    }
    O[qoff + lane] = o0 * inv;
    O[qoff + lane + 32] = o1 * inv;
}

// ---------------- final projection: (32768,512) @ (512,21) + bout --------------
__global__ void out_k(const float* __restrict__ Hx, const float* __restrict__ Wt,
                      const float* __restrict__ bout, float* __restrict__ out) {
    int w = (int)((blockIdx.x * blockDim.x + threadIdx.x) >> 5);
    int lane = threadIdx.x & 31;
    if (w >= Mrows) return;
    const float* hr = Hx + (size_t)w * Dc;
    float hv[16];
#pragma unroll
    for (int t = 0; t < 16; t++) hv[t] = hr[lane + 32 * t];
    for (int n = 0; n < Ac; n++) {
        float a = 0.f;
#pragma unroll
        for (int t = 0; t < 16; t++) a += hv[t] * Wt[(lane + 32 * t) * Ac + n];
#pragma unroll
        for (int o = 16; o; o >>= 1) a += __shfl_xor_sync(0xffffffffu, a, o);
        if (lane == 0) out[(size_t)w * Ac + n] = a + bout[n];
    }
}

// ---------------- launch ----------------
extern "C" void kernel_launch(void* const* d_in, const int* in_sizes, int n_in,
                              void* d_out, int out_size) {
    const int*   x    = (const int*)d_in[0];
    // d_in[1] = mask (bool junction-tree mask) — structure is hardcoded, unused
    const float* tok  = (const float*)d_in[2];
    const float* pos  = (const float*)d_in[3];
    const float* wq   = (const float*)d_in[4];
    const float* bq   = (const float*)d_in[5];
    const float* wk   = (const float*)d_in[6];
    const float* bk   = (const float*)d_in[7];
    const float* wv   = (const float*)d_in[8];
    const float* bv   = (const float*)d_in[9];
    const float* wo   = (const float*)d_in[10];
    const float* bo   = (const float*)d_in[11];
    const float* ln1s = (const float*)d_in[12];
    const float* ln1b = (const float*)d_in[13];
    const float* ln2s = (const float*)d_in[14];
    const float* ln2b = (const float*)d_in[15];
    const float* w1   = (const float*)d_in[16];
    const float* b1   = (const float*)d_in[17];
    const float* w2   = (const float*)d_in[18];
    const float* b2   = (const float*)d_in[19];
    const float* wout = (const float*)d_in[20];
    const float* bout = (const float*)d_in[21];
    float* outp = (float*)d_out;

    float *hb, *nb, *qb, *kb, *vb, *fb;
    cudaGetSymbolAddress((void**)&hb, g_h);
    cudaGetSymbolAddress((void**)&nb, g_n);
    cudaGetSymbolAddress((void**)&qb, g_q);
    cudaGetSymbolAddress((void**)&kb, g_k);
    cudaGetSymbolAddress((void**)&vb, g_v);
    cudaGetSymbolAddress((void**)&fb, g_f);

    const int T = 256;
    // embedding
    embed_k<<<(Mrows * (Dc / 4) + T - 1) / T, T>>>(x, tok, pos, hb);

    dim3 gQKV(Dc / 128, Mrows / 128);    // (4, 256)
    dim3 gFF1(DFFc / 128, Mrows / 128);  // (16, 256)

    for (int l = 0; l < NLc; l++) {
        const float* Wq = wq + (size_t)l * Dc * Dc;
        const float* Wk = wk + (size_t)l * Dc * Dc;
        const float* Wv = wv + (size_t)l * Dc * Dc;
        const float* Wo = wo + (size_t)l * Dc * Dc;
        const float* W1 = w1 + (size_t)l * Dc * DFFc;
        const float* W2 = w2 + (size_t)l * DFFc * Dc;

        ln_k<<<Mrows / 8, T>>>(hb, ln1s + l * Dc, ln1b + l * Dc, nb);
        gemm_k<0><<<gQKV, T>>>(nb, Wq, bq + l * Dc, nullptr, qb, Mrows, Dc, Dc);
        gemm_k<0><<<gQKV, T>>>(nb, Wk, bk + l * Dc, nullptr, kb, Mrows, Dc, Dc);
        gemm_k<0><<<gQKV, T>>>(nb, Wv, bv + l * Dc, nullptr, vb, Mrows, Dc, Dc);
        attn_k<<<(Mrows * Hc) / 8, T>>>(qb, kb, vb, nb);  // nb = attention output
        gemm_k<2><<<gQKV, T>>>(nb, Wo, bo + l * Dc, hb, hb, Mrows, Dc, Dc);
        ln_k<<<Mrows / 8, T>>>(hb, ln2s + l * Dc, ln2b + l * Dc, nb);
        gemm_k<1><<<gFF1, T>>>(nb, W1, b1 + l * DFFc, nullptr, fb, Mrows, DFFc, Dc);
        gemm_k<2><<<gQKV, T>>>(fb, W2, b2 + l * Dc, hb, hb, Mrows, Dc, DFFc);
    }

    out_k<<<Mrows / 8, T>>>(hb, wout, bout, outp);
}

// round 3
// speedup vs baseline: 2.6309x; 2.6309x over previous
#include <cuda_runtime.h>
#include <cuda_fp16.h>
#include <math.h>
#include <stdint.h>

// Problem constants
#define Bc   32
#define Lc   1024
#define Dc   512
#define Hc   8
#define DHc  64
#define DFFc 2048
#define NLc  6
#define Ac   21
#define Mrows (Bc*Lc)   // 32768

// ---------------- PTX helpers ----------------
__device__ __forceinline__ uint32_t smem_u32(const void* p) {
    uint32_t a;
    asm("{ .reg .u64 t; cvta.to.shared.u64 t, %1; cvt.u32.u64 %0, t; }" : "=r"(a) : "l"(p));
    return a;
}
__device__ __forceinline__ void ldm_x4(uint32_t* r, uint32_t addr) {
    asm volatile("ldmatrix.sync.aligned.m8n8.x4.shared.b16 {%0,%1,%2,%3}, [%4];"
                 : "=r"(r[0]), "=r"(r[1]), "=r"(r[2]), "=r"(r[3]) : "r"(addr));
}
__device__ __forceinline__ void ldm_x2(uint32_t* r, uint32_t addr) {
    asm volatile("ldmatrix.sync.aligned.m8n8.x2.shared.b16 {%0,%1}, [%2];"
                 : "=r"(r[0]), "=r"(r[1]) : "r"(addr));
}
__device__ __forceinline__ void mma16816(float* d, const uint32_t* a, const uint32_t* b) {
    asm volatile("mma.sync.aligned.m16n8k16.row.col.f32.f16.f16.f32 "
                 "{%0,%1,%2,%3}, {%4,%5,%6,%7}, {%8,%9}, {%0,%1,%2,%3};"
                 : "+f"(d[0]), "+f"(d[1]), "+f"(d[2]), "+f"(d[3])
                 : "r"(a[0]), "r"(a[1]), "r"(a[2]), "r"(a[3]), "r"(b[0]), "r"(b[1]));
}
#define CP_ASYNC16(dst, src) asm volatile("cp.async.cg.shared.global [%0], [%1], 16;" :: "r"(dst), "l"(src))
#define CP_COMMIT()          asm volatile("cp.async.commit_group;" ::: "memory")
#define CP_WAIT1()           asm volatile("cp.async.wait_group 1;" ::: "memory")

// ---------------- scratch ----------------
__device__ float g_h[(size_t)Mrows * Dc];          // residual fp32
__device__ float g_qkv[(size_t)Mrows * 3 * Dc];    // fused QKV fp32
__device__ __half g_nh[(size_t)Mrows * Dc];        // activation hi
__device__ __half g_nl[(size_t)Mrows * Dc];        // activation lo
__device__ __half g_fh[(size_t)Mrows * DFFc];
__device__ __half g_fl[(size_t)Mrows * DFFc];
// transposed split weights: [qkv 6*1536*512][wo 6*512*512][w1 6*2048*512][w2 6*512*2048]
#define OFF_QKV 0
#define OFF_WO  4718592
#define OFF_W1  6291456
#define OFF_W2  12582912
#define WT_TOT  18874368
__device__ __half g_wth[WT_TOT];
__device__ __half g_wtl[WT_TOT];
__device__ float g_bqkv[NLc * 3 * Dc];

// ---------------- embedding ----------------
__global__ void embed_k(const int* __restrict__ x, const float* __restrict__ tok,
                        const float* __restrict__ pos, float* __restrict__ h) {
    size_t i = (size_t)blockIdx.x * blockDim.x + threadIdx.x;
    const size_t total = (size_t)Mrows * (Dc / 4);
    if (i >= total) return;
    size_t row = i / (Dc / 4);
    int c4 = (int)(i % (Dc / 4));
    int t = x[row];
    int l = (int)(row & (Lc - 1));
    float4 a = ((const float4*)tok)[(size_t)t * (Dc / 4) + c4];
    float4 p = ((const float4*)pos)[(size_t)l * (Dc / 4) + c4];
    float4 o; o.x = a.x + p.x; o.y = a.y + p.y; o.z = a.z + p.z; o.w = a.w + p.w;
    ((float4*)h)[i] = o;
}

// ---------------- weight transpose + fp16 split: W[K,N] -> T[N,K] hi/lo ----------
__global__ void wconv_k(const float* __restrict__ W, __half* __restrict__ Th,
                        __half* __restrict__ Tl, int K, int N) {
    __shared__ float t[32][33];
    int k0 = blockIdx.y * 32, n0 = blockIdx.x * 32;
    int tx = threadIdx.x, ty = threadIdx.y;  // 32 x 8
#pragma unroll
    for (int i = 0; i < 4; i++)
        t[ty + 8 * i][tx] = W[(size_t)(k0 + ty + 8 * i) * N + n0 + tx];
    __syncthreads();
#pragma unroll
    for (int i = 0; i < 4; i++) {
        float v = t[tx][ty + 8 * i];
        __half hh = __float2half_rn(v);
        float lo = v - __half2float(hh);
        size_t o = (size_t)(n0 + ty + 8 * i) * K + k0 + tx;
        Th[o] = hh;
        Tl[o] = __float2half_rn(lo);
    }
}

__global__ void bqkv_k(const float* __restrict__ bq, const float* __restrict__ bk,
                       const float* __restrict__ bv, float* __restrict__ o) {
    int i = blockIdx.x * blockDim.x + threadIdx.x;
    if (i >= NLc * 3 * Dc) return;
    int l = i / (3 * Dc), c = i % (3 * Dc);
    float v = (c < Dc) ? bq[l * Dc + c] : (c < 2 * Dc) ? bk[l * Dc + c - Dc] : bv[l * Dc + c - 2 * Dc];
    o[i] = v;
}

// ---------------- layernorm -> split fp16 ----------------
__global__ void ln_hf_k(const float* __restrict__ X, const float* __restrict__ gs,
                        const float* __restrict__ gb, __half* __restrict__ Yh,
                        __half* __restrict__ Yl) {
    int w = (int)((blockIdx.x * blockDim.x + threadIdx.x) >> 5);
    int lane = threadIdx.x & 31;
    if (w >= Mrows) return;
    const float* x = X + (size_t)w * Dc;
    float4 v[4];
    float s = 0.f;
#pragma unroll
    for (int t = 0; t < 4; t++) {
        v[t] = ((const float4*)x)[lane + 32 * t];
        s += v[t].x + v[t].y + v[t].z + v[t].w;
    }
#pragma unroll
    for (int o = 16; o; o >>= 1) s += __shfl_xor_sync(0xffffffffu, s, o);
    float mu = s * (1.0f / Dc);
    float ss = 0.f;
#pragma unroll
    for (int t = 0; t < 4; t++) {
        float dx = v[t].x - mu, dy = v[t].y - mu, dz = v[t].z - mu, dw = v[t].w - mu;
        ss += dx * dx + dy * dy + dz * dz + dw * dw;
    }
#pragma unroll
    for (int o = 16; o; o >>= 1) ss += __shfl_xor_sync(0xffffffffu, ss, o);
    float rs = rsqrtf(ss * (1.0f / Dc) + 1e-6f);
#pragma unroll
    for (int t = 0; t < 4; t++) {
        int f4 = lane + 32 * t;
        float4 g4 = ((const float4*)gs)[f4];
        float4 b4 = ((const float4*)gb)[f4];
        float y0 = (v[t].x - mu) * rs * g4.x + b4.x;
        float y1 = (v[t].y - mu) * rs * g4.y + b4.y;
        float y2 = (v[t].z - mu) * rs * g4.z + b4.z;
        float y3 = (v[t].w - mu) * rs * g4.w + b4.w;
        __half h0 = __float2half_rn(y0), h1 = __float2half_rn(y1);
        __half h2 = __float2half_rn(y2), h3 = __float2half_rn(y3);
        __half2 ph0; ph0.x = h0; ph0.y = h1;
        __half2 ph1; ph1.x = h2; ph1.y = h3;
        __half2 pl0;
        pl0.x = __float2half_rn(y0 - __half2float(h0));
        pl0.y = __float2half_rn(y1 - __half2float(h1));
        __half2 pl1;
        pl1.x = __float2half_rn(y2 - __half2float(h2));
        pl1.y = __float2half_rn(y3 - __half2float(h3));
        size_t base = (size_t)w * Dc + f4 * 4;
        *(__half2*)(Yh + base) = ph0;
        *(__half2*)(Yh + base + 2) = ph1;
        *(__half2*)(Yl + base) = pl0;
        *(__half2*)(Yl + base + 2) = pl1;
    }
}

// ---------------- fast accurate gelu (tanh form via expf) ----------------
__device__ __forceinline__ float gelu_fast(float x) {
    // 2u = x*(c1 + c2*x^2), tanh(u) = 1 - 2/(e^{2u}+1), gelu = x - x/(e^{2u}+1)
    float v = x * (1.5957691216057308f + 0.07135660900000000f * x * x);
    float e = __expf(v);
    return x - __fdividef(x, e + 1.0f);
}

// ---------------- split-fp16 HMMA GEMM ----------------
// C[M,N] = A[M,K] @ B^T, B stored [N,K]. A,B given as hi/lo fp16.
// EPI 0: Cf = acc + bias;  EPI 1: Ch/Cl = split(gelu(acc+bias));  EPI 2: Cf = acc+bias+R
#define STG_BYTES 65536  // 4 tiles x 16KB

template <int EPI>
__global__ void __launch_bounds__(256, 1) gemm_hm(
    const __half* __restrict__ Ah, const __half* __restrict__ Al,
    const __half* __restrict__ Bh, const __half* __restrict__ Bl,
    const float* __restrict__ bias, const float* __restrict__ R,
    float* __restrict__ Cf, __half* __restrict__ Ch, __half* __restrict__ Cl,
    int M, int N, int K) {
    extern __shared__ char smraw[];
    uint32_t sb = smem_u32(smraw);
    uint32_t S = (sb + 1023) & ~1023u;  // 1024-aligned smem base

    const int tid = threadIdx.x;
    const int lane = tid & 31;
    const int wid = tid >> 5;
    const int warpM = wid >> 2;   // 0..1
    const int warpN = wid & 3;    // 0..3

    const size_t mBase = (size_t)blockIdx.y * 128;
    const size_t nBase = (size_t)blockIdx.x * 128;
    const int nch = K >> 6;

    // per-thread ldmatrix offsets
    uint32_t aRow[4], bRow[4];
#pragma unroll
    for (int mt = 0; mt < 4; mt++) aRow[mt] = (warpM * 64 + mt * 16 + (lane & 15)) * 128;
#pragma unroll
    for (int nt = 0; nt < 4; nt++) bRow[nt] = (warpN * 32 + nt * 8 + (lane & 7)) * 128;
    int axor = lane >> 4;
    int bxor = (lane >> 3) & 1;
    int lsw = lane & 7;
    uint32_t aCh[4], bCh[4];
#pragma unroll
    for (int ks = 0; ks < 4; ks++) {
        aCh[ks] = (uint32_t)(((2 * ks + axor) ^ lsw) << 4);
        bCh[ks] = (uint32_t)(((2 * ks + bxor) ^ lsw) << 4);
    }

    float acc[4][4][4];
#pragma unroll
    for (int i = 0; i < 4; i++)
#pragma unroll
        for (int j = 0; j < 4; j++)
#pragma unroll
            for (int t = 0; t < 4; t++) acc[i][j][t] = 0.f;

    // stage loader (cp.async): tiles 0=Ah 1=Al 2=Bh 3=Bl, 128 rows x 64 halves, swizzled
    auto load_stage = [&](int buf, int ch) {
        uint32_t sdst = S + buf * STG_BYTES;
#pragma unroll
        for (int u = 0; u < 16; u++) {
            int tile = u >> 2;
            int r = (u & 3) * 32 + (tid >> 3);
            int j = tid & 7;
            const __half* src = (tile == 0) ? Ah : (tile == 1) ? Al : (tile == 2) ? Bh : Bl;
            size_t rb = ((tile < 2) ? mBase : nBase) + r;
            const void* gsrc = src + rb * (size_t)K + (size_t)ch * 64 + j * 8;
            uint32_t d = sdst + tile * 16384 + r * 128 + (((uint32_t)(j ^ (r & 7))) << 4);
            CP_ASYNC16(d, gsrc);
        }
    };

    load_stage(0, 0); CP_COMMIT();
    load_stage(1, 1); CP_COMMIT();

    for (int ch = 0; ch < nch; ch++) {
        CP_WAIT1();
        __syncthreads();
        uint32_t base = S + (ch & 1) * STG_BYTES;
#pragma unroll
        for (int ks = 0; ks < 4; ks++) {
            uint32_t ah[4][4], al[4][4], bh[4][2], bl[4][2];
#pragma unroll
            for (int mt = 0; mt < 4; mt++) ldm_x4(ah[mt], base + aRow[mt] + aCh[ks]);
#pragma unroll
            for (int mt = 0; mt < 4; mt++) ldm_x4(al[mt], base + 16384 + aRow[mt] + aCh[ks]);
#pragma unroll
            for (int nt = 0; nt < 4; nt++) ldm_x2(bh[nt], base + 32768 + bRow[nt] + bCh[ks]);
#pragma unroll
            for (int nt = 0; nt < 4; nt++) ldm_x2(bl[nt], base + 49152 + bRow[nt] + bCh[ks]);
#pragma unroll
            for (int mt = 0; mt < 4; mt++)
#pragma unroll
                for (int nt = 0; nt < 4; nt++) {
                    mma16816(acc[mt][nt], ah[mt], bh[nt]);
                    mma16816(acc[mt][nt], al[mt], bh[nt]);
                    mma16816(acc[mt][nt], ah[mt], bl[nt]);
                }
        }
        __syncthreads();
        if (ch + 2 < nch) load_stage(ch & 1, ch + 2);
        CP_COMMIT();
    }

    // epilogue
    int r = lane >> 2;
    int cc = (lane & 3) * 2;
#pragma unroll
    for (int mt = 0; mt < 4; mt++) {
        size_t row0 = mBase + warpM * 64 + mt * 16 + r;
#pragma unroll
        for (int hf = 0; hf < 2; hf++) {
            size_t row = row0 + hf * 8;
#pragma unroll
            for (int nt = 0; nt < 4; nt++) {
                int col = (int)nBase + warpN * 32 + nt * 8 + cc;
                float v0 = acc[mt][nt][hf * 2 + 0] + bias[col];
                float v1 = acc[mt][nt][hf * 2 + 1] + bias[col + 1];
                if (EPI == 1) {
                    v0 = gelu_fast(v0);
                    v1 = gelu_fast(v1);
                    __half h0 = __float2half_rn(v0), h1 = __float2half_rn(v1);
                    __half2 ph; ph.x = h0; ph.y = h1;
                    __half2 pl;
                    pl.x = __float2half_rn(v0 - __half2float(h0));
                    pl.y = __float2half_rn(v1 - __half2float(h1));
                    size_t o = row * (size_t)N + col;
                    *(__half2*)(Ch + o) = ph;
                    *(__half2*)(Cl + o) = pl;
                } else {
                    size_t o = row * (size_t)N + col;
                    if (EPI == 2) {
                        float2 rv = *(const float2*)(R + o);
                        v0 += rv.x; v1 += rv.y;
                    }
                    float2 ov; ov.x = v0; ov.y = v1;
                    *(float2*)(Cf + o) = ov;
                }
            }
        }
    }
}

// ---------------- junction-tree attention (QKV fused layout, fp16 split out) ------
__global__ void attn_k(const float* __restrict__ QKV, __half* __restrict__ Oh,
                       __half* __restrict__ Ol) {
    int gw = (int)((blockIdx.x * blockDim.x + threadIdx.x) >> 5);  // bl*H + h
    int lane = threadIdx.x & 31;
    int h = gw & (Hc - 1);
    int bl = gw >> 3;
    int l = bl & (Lc - 1);
    int c = l >> 2, rr = l & 3;

    int keys[8];
    int nk = 0;
    if (c > 0) {
        int p = (c - 1) << 2;
        keys[0] = p; keys[1] = p + 1; keys[2] = p + 2; keys[3] = p + 3;
        nk = 4;
    }
    int ob = c << 2;
#pragma unroll
    for (int t = 0; t < 4; t++)
        if (t <= rr) keys[nk++] = ob + t;

    int blBase = bl - l;
    size_t qoff = (size_t)bl * (3 * Dc) + h * DHc;
    float q0 = QKV[qoff + lane];
    float q1 = QKV[qoff + lane + 32];

    float s[8];
    for (int j = 0; j < nk; j++) {
        size_t ko = (size_t)(blBase + keys[j]) * (3 * Dc) + Dc + h * DHc;
        float d = q0 * QKV[ko + lane] + q1 * QKV[ko + lane + 32];
#pragma unroll
        for (int o = 16; o; o >>= 1) d += __shfl_xor_sync(0xffffffffu, d, o);
        s[j] = d * 0.125f;
    }
    float mx = s[0];
    for (int j = 1; j < nk; j++) mx = fmaxf(mx, s[j]);
    float sum = 0.f;
    for (int j = 0; j < nk; j++) { s[j] = expf(s[j] - mx); sum += s[j]; }
    float inv = 1.0f / sum;
    float o0 = 0.f, o1 = 0.f;
    for (int j = 0; j < nk; j++) {
        size_t vo = (size_t)(blBase + keys[j]) * (3 * Dc) + 2 * Dc + h * DHc;
        o0 += s[j] * QKV[vo + lane];
        o1 += s[j] * QKV[vo + lane + 32];
    }
    o0 *= inv; o1 *= inv;
    size_t oo = (size_t)bl * Dc + h * DHc + lane;
    __half h0 = __float2half_rn(o0);
    __half h1 = __float2half_rn(o1);
    Oh[oo] = h0;
    Oh[oo + 32] = h1;
    Ol[oo] = __float2half_rn(o0 - __half2float(h0));
    Ol[oo + 32] = __float2half_rn(o1 - __half2float(h1));
}

// ---------------- final projection ----------------
__global__ void out_k(const float* __restrict__ Hx, const float* __restrict__ Wt,
                      const float* __restrict__ bout, float* __restrict__ out) {
    int w = (int)((blockIdx.x * blockDim.x + threadIdx.x) >> 5);
    int lane = threadIdx.x & 31;
    if (w >= Mrows) return;
    const float* hr = Hx + (size_t)w * Dc;
    float hv[16];
#pragma unroll
    for (int t = 0; t < 16; t++) hv[t] = hr[lane + 32 * t];
    for (int n = 0; n < Ac; n++) {
        float a = 0.f;
#pragma unroll
        for (int t = 0; t < 16; t++) a += hv[t] * Wt[(lane + 32 * t) * Ac + n];
#pragma unroll
        for (int o = 16; o; o >>= 1) a += __shfl_xor_sync(0xffffffffu, a, o);
        if (lane == 0) out[(size_t)w * Ac + n] = a + bout[n];
    }
}

// ---------------- launch ----------------
extern "C" void kernel_launch(void* const* d_in, const int* in_sizes, int n_in,
                              void* d_out, int out_size) {
    const int*   x    = (const int*)d_in[0];
    const float* tok  = (const float*)d_in[2];
    const float* pos  = (const float*)d_in[3];
    const float* wq   = (const float*)d_in[4];
    const float* bq   = (const float*)d_in[5];
    const float* wk   = (const float*)d_in[6];
    const float* bk   = (const float*)d_in[7];
    const float* wv   = (const float*)d_in[8];
    const float* bv   = (const float*)d_in[9];
    const float* wo   = (const float*)d_in[10];
    const float* bo   = (const float*)d_in[11];
    const float* ln1s = (const float*)d_in[12];
    const float* ln1b = (const float*)d_in[13];
    const float* ln2s = (const float*)d_in[14];
    const float* ln2b = (const float*)d_in[15];
    const float* w1   = (const float*)d_in[16];
    const float* b1   = (const float*)d_in[17];
    const float* w2   = (const float*)d_in[18];
    const float* b2   = (const float*)d_in[19];
    const float* wout = (const float*)d_in[20];
    const float* bout = (const float*)d_in[21];
    float* outp = (float*)d_out;

    float *hb, *qkvb, *bqkvb;
    __half *nh, *nl, *fh, *fl, *wth, *wtl;
    cudaGetSymbolAddress((void**)&hb, g_h);
    cudaGetSymbolAddress((void**)&qkvb, g_qkv);
    cudaGetSymbolAddress((void**)&bqkvb, g_bqkv);
    cudaGetSymbolAddress((void**)&nh, g_nh);
    cudaGetSymbolAddress((void**)&nl, g_nl);
    cudaGetSymbolAddress((void**)&fh, g_fh);
    cudaGetSymbolAddress((void**)&fl, g_fl);
    cudaGetSymbolAddress((void**)&wth, g_wth);
    cudaGetSymbolAddress((void**)&wtl, g_wtl);

    const int SMEM = 2 * STG_BYTES + 1024;
    static bool attr_done = false;
    if (!attr_done) {
        cudaFuncSetAttribute(gemm_hm<0>, cudaFuncAttributeMaxDynamicSharedMemorySize, SMEM);
        cudaFuncSetAttribute(gemm_hm<1>, cudaFuncAttributeMaxDynamicSharedMemorySize, SMEM);
        cudaFuncSetAttribute(gemm_hm<2>, cudaFuncAttributeMaxDynamicSharedMemorySize, SMEM);
        attr_done = true;
    }
    const int T = 256;

    // ---- weight conversion (transpose + fp16 split) ----
    {
        dim3 blk(32, 8);
        for (int l = 0; l < NLc; l++) {
            size_t qo = OFF_QKV + (size_t)l * 1536 * 512;
            wconv_k<<<dim3(16, 16), blk>>>(wq + (size_t)l * 512 * 512, wth + qo, wtl + qo, 512, 512);
            wconv_k<<<dim3(16, 16), blk>>>(wk + (size_t)l * 512 * 512, wth + qo + 512 * 512, wtl + qo + 512 * 512, 512, 512);
            wconv_k<<<dim3(16, 16), blk>>>(wv + (size_t)l * 512 * 512, wth + qo + 1024 * 512, wtl + qo + 1024 * 512, 512, 512);
            size_t oo = OFF_WO + (size_t)l * 512 * 512;
            wconv_k<<<dim3(16, 16), blk>>>(wo + (size_t)l * 512 * 512, wth + oo, wtl + oo, 512, 512);
            size_t o1 = OFF_W1 + (size_t)l * 2048 * 512;
            wconv_k<<<dim3(64, 16), blk>>>(w1 + (size_t)l * 512 * 2048, wth + o1, wtl + o1, 512, 2048);
            size_t o2 = OFF_W2 + (size_t)l * 512 * 2048;
            wconv_k<<<dim3(16, 64), blk>>>(w2 + (size_t)l * 2048 * 512, wth + o2, wtl + o2, 2048, 512);
        }
        bqkv_k<<<(NLc * 3 * Dc + T - 1) / T, T>>>(bq, bk, bv, bqkvb);
    }

    embed_k<<<(Mrows * (Dc / 4) + T - 1) / T, T>>>(x, tok, pos, hb);

    dim3 gQKV(1536 / 128, Mrows / 128);  // (12, 256)
    dim3 gD(Dc / 128, Mrows / 128);      // (4, 256)
    dim3 gFF(DFFc / 128, Mrows / 128);   // (16, 256)

    for (int l = 0; l < NLc; l++) {
        size_t qo = OFF_QKV + (size_t)l * 1536 * 512;
        size_t oo = OFF_WO + (size_t)l * 512 * 512;
        size_t o1 = OFF_W1 + (size_t)l * 2048 * 512;
        size_t o2 = OFF_W2 + (size_t)l * 512 * 2048;

        ln_hf_k<<<Mrows / 8, T>>>(hb, ln1s + l * Dc, ln1b + l * Dc, nh, nl);
        gemm_hm<0><<<gQKV, T, SMEM>>>(nh, nl, wth + qo, wtl + qo, bqkvb + l * 1536,
                                      nullptr, qkvb, nullptr, nullptr, Mrows, 1536, 512);
        attn_k<<<(Mrows * Hc) / 8, T>>>(qkvb, nh, nl);
        gemm_hm<2><<<gD, T, SMEM>>>(nh, nl, wth + oo, wtl + oo, bo + l * Dc,
                                    hb, hb, nullptr, nullptr, Mrows, 512, 512);
        ln_hf_k<<<Mrows / 8, T>>>(hb, ln2s + l * Dc, ln2b + l * Dc, nh, nl);
        gemm_hm<1><<<gFF, T, SMEM>>>(nh, nl, wth + o1, wtl + o1, b1 + l * DFFc,
                                     nullptr, nullptr, fh, fl, Mrows, 2048, 512);
        gemm_hm<2><<<gD, T, SMEM>>>(fh, fl, wth + o2, wtl + o2, b2 + l * Dc,
                                    hb, hb, nullptr, nullptr, Mrows, 512, 2048);
    }

    out_k<<<Mrows / 8, T>>>(hb, wout, bout, outp);
}

// round 4
// speedup vs baseline: 2.6826x; 1.0196x over previous
#include <cuda_runtime.h>
#include <cuda_fp16.h>
#include <math.h>
#include <stdint.h>

// Problem constants
#define Bc   32
#define Lc   1024
#define Dc   512
#define Hc   8
#define DHc  64
#define DFFc 2048
#define NLc  6
#define Ac   21
#define Mrows (Bc*Lc)   // 32768

// ---------------- PTX helpers ----------------
__device__ __forceinline__ uint32_t smem_u32(const void* p) {
    uint32_t a;
    asm("{ .reg .u64 t; cvta.to.shared.u64 t, %1; cvt.u32.u64 %0, t; }" : "=r"(a) : "l"(p));
    return a;
}
__device__ __forceinline__ void ldm_x4(uint32_t* r, uint32_t addr) {
    asm volatile("ldmatrix.sync.aligned.m8n8.x4.shared.b16 {%0,%1,%2,%3}, [%4];"
                 : "=r"(r[0]), "=r"(r[1]), "=r"(r[2]), "=r"(r[3]) : "r"(addr));
}
__device__ __forceinline__ void ldm_x2(uint32_t* r, uint32_t addr) {
    asm volatile("ldmatrix.sync.aligned.m8n8.x2.shared.b16 {%0,%1}, [%2];"
                 : "=r"(r[0]), "=r"(r[1]) : "r"(addr));
}
__device__ __forceinline__ void mma16816(float* d, const uint32_t* a, const uint32_t* b) {
    asm volatile("mma.sync.aligned.m16n8k16.row.col.f32.f16.f16.f32 "
                 "{%0,%1,%2,%3}, {%4,%5,%6,%7}, {%8,%9}, {%0,%1,%2,%3};"
                 : "+f"(d[0]), "+f"(d[1]), "+f"(d[2]), "+f"(d[3])
                 : "r"(a[0]), "r"(a[1]), "r"(a[2]), "r"(a[3]), "r"(b[0]), "r"(b[1]));
}
#define CP_ASYNC16(dst, src) asm volatile("cp.async.cg.shared.global [%0], [%1], 16;" :: "r"(dst), "l"(src))
#define CP_COMMIT()          asm volatile("cp.async.commit_group;" ::: "memory")
#define CP_WAIT1()           asm volatile("cp.async.wait_group 1;" ::: "memory")

// ---------------- scratch ----------------
__device__ float g_h[(size_t)Mrows * Dc];          // residual fp32
__device__ float g_qkv[(size_t)Mrows * 3 * Dc];    // fused QKV fp32
__device__ __half g_nh[(size_t)Mrows * Dc];        // activation hi
__device__ __half g_nl[(size_t)Mrows * Dc];        // activation lo
__device__ __half g_fh[(size_t)Mrows * DFFc];
__device__ __half g_fl[(size_t)Mrows * DFFc];
// transposed split weights: [qkv 6*1536*512][wo 6*512*512][w1 6*2048*512][w2 6*512*2048]
#define OFF_QKV 0
#define OFF_WO  4718592
#define OFF_W1  6291456
#define OFF_W2  12582912
#define WT_TOT  18874368
__device__ __half g_wth[WT_TOT];
__device__ __half g_wtl[WT_TOT];
__device__ float g_bqkv[NLc * 3 * Dc];

// ---------------- embedding ----------------
__global__ void embed_k(const int* __restrict__ x, const float* __restrict__ tok,
                        const float* __restrict__ pos, float* __restrict__ h) {
    size_t i = (size_t)blockIdx.x * blockDim.x + threadIdx.x;
    const size_t total = (size_t)Mrows * (Dc / 4);
    if (i >= total) return;
    size_t row = i / (Dc / 4);
    int c4 = (int)(i % (Dc / 4));
    int t = x[row];
    int l = (int)(row & (Lc - 1));
    float4 a = ((const float4*)tok)[(size_t)t * (Dc / 4) + c4];
    float4 p = ((const float4*)pos)[(size_t)l * (Dc / 4) + c4];
    float4 o; o.x = a.x + p.x; o.y = a.y + p.y; o.z = a.z + p.z; o.w = a.w + p.w;
    ((float4*)h)[i] = o;
}

// ---------------- weight transpose + fp16 split: W[K,N] -> T[N,K] hi/lo ----------
__global__ void wconv_k(const float* __restrict__ W, __half* __restrict__ Th,
                        __half* __restrict__ Tl, int K, int N) {
    __shared__ float t[32][33];
    int k0 = blockIdx.y * 32, n0 = blockIdx.x * 32;
    int tx = threadIdx.x, ty = threadIdx.y;  // 32 x 8
#pragma unroll
    for (int i = 0; i < 4; i++)
        t[ty + 8 * i][tx] = W[(size_t)(k0 + ty + 8 * i) * N + n0 + tx];
    __syncthreads();
#pragma unroll
    for (int i = 0; i < 4; i++) {
        float v = t[tx][ty + 8 * i];
        __half hh = __float2half_rn(v);
        float lo = v - __half2float(hh);
        size_t o = (size_t)(n0 + ty + 8 * i) * K + k0 + tx;
        Th[o] = hh;
        Tl[o] = __float2half_rn(lo);
    }
}

__global__ void bqkv_k(const float* __restrict__ bq, const float* __restrict__ bk,
                       const float* __restrict__ bv, float* __restrict__ o) {
    int i = blockIdx.x * blockDim.x + threadIdx.x;
    if (i >= NLc * 3 * Dc) return;
    int l = i / (3 * Dc), c = i % (3 * Dc);
    float v = (c < Dc) ? bq[l * Dc + c] : (c < 2 * Dc) ? bk[l * Dc + c - Dc] : bv[l * Dc + c - 2 * Dc];
    o[i] = v;
}

// ---------------- layernorm -> split fp16 ----------------
__global__ void ln_hf_k(const float* __restrict__ X, const float* __restrict__ gs,
                        const float* __restrict__ gb, __half* __restrict__ Yh,
                        __half* __restrict__ Yl) {
    int w = (int)((blockIdx.x * blockDim.x + threadIdx.x) >> 5);
    int lane = threadIdx.x & 31;
    if (w >= Mrows) return;
    const float* x = X + (size_t)w * Dc;
    float4 v[4];
    float s = 0.f;
#pragma unroll
    for (int t = 0; t < 4; t++) {
        v[t] = ((const float4*)x)[lane + 32 * t];
        s += v[t].x + v[t].y + v[t].z + v[t].w;
    }
#pragma unroll
    for (int o = 16; o; o >>= 1) s += __shfl_xor_sync(0xffffffffu, s, o);
    float mu = s * (1.0f / Dc);
    float ss = 0.f;
#pragma unroll
    for (int t = 0; t < 4; t++) {
        float dx = v[t].x - mu, dy = v[t].y - mu, dz = v[t].z - mu, dw = v[t].w - mu;
        ss += dx * dx + dy * dy + dz * dz + dw * dw;
    }
#pragma unroll
    for (int o = 16; o; o >>= 1) ss += __shfl_xor_sync(0xffffffffu, ss, o);
    float rs = rsqrtf(ss * (1.0f / Dc) + 1e-6f);
#pragma unroll
    for (int t = 0; t < 4; t++) {
        int f4 = lane + 32 * t;
        float4 g4 = ((const float4*)gs)[f4];
        float4 b4 = ((const float4*)gb)[f4];
        float y0 = (v[t].x - mu) * rs * g4.x + b4.x;
        float y1 = (v[t].y - mu) * rs * g4.y + b4.y;
        float y2 = (v[t].z - mu) * rs * g4.z + b4.z;
        float y3 = (v[t].w - mu) * rs * g4.w + b4.w;
        __half h0 = __float2half_rn(y0), h1 = __float2half_rn(y1);
        __half h2 = __float2half_rn(y2), h3 = __float2half_rn(y3);
        __half2 ph0; ph0.x = h0; ph0.y = h1;
        __half2 ph1; ph1.x = h2; ph1.y = h3;
        __half2 pl0;
        pl0.x = __float2half_rn(y0 - __half2float(h0));
        pl0.y = __float2half_rn(y1 - __half2float(h1));
        __half2 pl1;
        pl1.x = __float2half_rn(y2 - __half2float(h2));
        pl1.y = __float2half_rn(y3 - __half2float(h3));
        size_t base = (size_t)w * Dc + f4 * 4;
        *(__half2*)(Yh + base) = ph0;
        *(__half2*)(Yh + base + 2) = ph1;
        *(__half2*)(Yl + base) = pl0;
        *(__half2*)(Yl + base + 2) = pl1;
    }
}

// ---------------- fast accurate gelu (tanh form via expf) ----------------
__device__ __forceinline__ float gelu_fast(float x) {
    float v = x * (1.5957691216057308f + 0.07135660900000000f * x * x);
    float e = __expf(v);
    return x - __fdividef(x, e + 1.0f);
}

// ---------------- split-fp16 HMMA GEMM (3-stage pipe, term-major MMA) ----------
// C[M,N] = A[M,K] @ B^T, B stored [N,K]. A,B given as hi/lo fp16.
// EPI 0: Cf = acc + bias;  EPI 1: Ch/Cl = split(gelu(acc+bias));  EPI 2: Cf = acc+bias+R
#define STG_BYTES 65536  // 4 tiles x 16KB
#define NSTG 3

template <int EPI>
__global__ void __launch_bounds__(256, 1) gemm_hm(
    const __half* __restrict__ Ah, const __half* __restrict__ Al,
    const __half* __restrict__ Bh, const __half* __restrict__ Bl,
    const float* __restrict__ bias, const float* __restrict__ R,
    float* __restrict__ Cf, __half* __restrict__ Ch, __half* __restrict__ Cl,
    int M, int N, int K) {
    extern __shared__ char smraw[];
    uint32_t sb = smem_u32(smraw);
    uint32_t S = (sb + 1023) & ~1023u;  // 1024-aligned smem base

    const int tid = threadIdx.x;
    const int lane = tid & 31;
    const int wid = tid >> 5;
    const int warpM = wid >> 2;   // 0..1
    const int warpN = wid & 3;    // 0..3

    const size_t mBase = (size_t)blockIdx.y * 128;
    const size_t nBase = (size_t)blockIdx.x * 128;
    const int nch = K >> 6;

    // per-thread ldmatrix offsets
    uint32_t aRow[4], bRow[4];
#pragma unroll
    for (int mt = 0; mt < 4; mt++) aRow[mt] = (warpM * 64 + mt * 16 + (lane & 15)) * 128;
#pragma unroll
    for (int nt = 0; nt < 4; nt++) bRow[nt] = (warpN * 32 + nt * 8 + (lane & 7)) * 128;
    int axor = lane >> 4;
    int bxor = (lane >> 3) & 1;
    int lsw = lane & 7;
    uint32_t aCh[4], bCh[4];
#pragma unroll
    for (int ks = 0; ks < 4; ks++) {
        aCh[ks] = (uint32_t)(((2 * ks + axor) ^ lsw) << 4);
        bCh[ks] = (uint32_t)(((2 * ks + bxor) ^ lsw) << 4);
    }

    float acc[4][4][4];
#pragma unroll
    for (int i = 0; i < 4; i++)
#pragma unroll
        for (int j = 0; j < 4; j++)
#pragma unroll
            for (int t = 0; t < 4; t++) acc[i][j][t] = 0.f;

    // stage loader (cp.async): tiles 0=Ah 1=Al 2=Bh 3=Bl, 128 rows x 64 halves, swizzled
    auto load_stage = [&](int slot, int ch) {
        uint32_t sdst = S + slot * STG_BYTES;
#pragma unroll
        for (int u = 0; u < 16; u++) {
            int tile = u >> 2;
            int r = (u & 3) * 32 + (tid >> 3);
            int j = tid & 7;
            const __half* src = (tile == 0) ? Ah : (tile == 1) ? Al : (tile == 2) ? Bh : Bl;
            size_t rb = ((tile < 2) ? mBase : nBase) + r;
            const void* gsrc = src + rb * (size_t)K + (size_t)ch * 64 + j * 8;
            uint32_t d = sdst + tile * 16384 + r * 128 + (((uint32_t)(j ^ (r & 7))) << 4);
            CP_ASYNC16(d, gsrc);
        }
    };

    // prologue: fill slot0, slot1
    load_stage(0, 0); CP_COMMIT();
    load_stage(1, 1); CP_COMMIT();

    int slot = 0;       // slot of chunk ch
    for (int ch = 0; ch < nch; ch++) {
        CP_WAIT1();          // chunk ch's copy done (<=1 group still pending)
        __syncthreads();     // data visible to all warps AND compute of ch-1 done
        // issue next-next chunk into the slot freed by ch-1
        int nslot = slot + 2; if (nslot >= NSTG) nslot -= NSTG;
        if (ch + 2 < nch) load_stage(nslot, ch + 2);
        CP_COMMIT();

        uint32_t base = S + slot * STG_BYTES;
#pragma unroll
        for (int ks = 0; ks < 4; ks++) {
            uint32_t ah[4][4], al[4][4], bh[4][2], bl[4][2];
            // HH operands first so term-0 MMAs can start immediately
#pragma unroll
            for (int mt = 0; mt < 4; mt++) ldm_x4(ah[mt], base + aRow[mt] + aCh[ks]);
#pragma unroll
            for (int nt = 0; nt < 4; nt++) ldm_x2(bh[nt], base + 32768 + bRow[nt] + bCh[ks]);
#pragma unroll
            for (int mt = 0; mt < 4; mt++) ldm_x4(al[mt], base + 16384 + aRow[mt] + aCh[ks]);
#pragma unroll
            for (int nt = 0; nt < 4; nt++) ldm_x2(bl[nt], base + 49152 + bRow[nt] + bCh[ks]);
            // term-major: 16 independent MMAs between any accumulator reuse
#pragma unroll
            for (int mt = 0; mt < 4; mt++)
#pragma unroll
                for (int nt = 0; nt < 4; nt++) mma16816(acc[mt][nt], ah[mt], bh[nt]);
#pragma unroll
            for (int mt = 0; mt < 4; mt++)
#pragma unroll
                for (int nt = 0; nt < 4; nt++) mma16816(acc[mt][nt], al[mt], bh[nt]);
#pragma unroll
            for (int mt = 0; mt < 4; mt++)
#pragma unroll
                for (int nt = 0; nt < 4; nt++) mma16816(acc[mt][nt], ah[mt], bl[nt]);
        }
        slot++; if (slot >= NSTG) slot = 0;
    }

    // epilogue
    int r = lane >> 2;
    int cc = (lane & 3) * 2;
#pragma unroll
    for (int mt = 0; mt < 4; mt++) {
        size_t row0 = mBase + warpM * 64 + mt * 16 + r;
#pragma unroll
        for (int hf = 0; hf < 2; hf++) {
            size_t row = row0 + hf * 8;
#pragma unroll
            for (int nt = 0; nt < 4; nt++) {
                int col = (int)nBase + warpN * 32 + nt * 8 + cc;
                float v0 = acc[mt][nt][hf * 2 + 0] + bias[col];
                float v1 = acc[mt][nt][hf * 2 + 1] + bias[col + 1];
                if (EPI == 1) {
                    v0 = gelu_fast(v0);
                    v1 = gelu_fast(v1);
                    __half h0 = __float2half_rn(v0), h1 = __float2half_rn(v1);
                    __half2 ph; ph.x = h0; ph.y = h1;
                    __half2 pl;
                    pl.x = __float2half_rn(v0 - __half2float(h0));
                    pl.y = __float2half_rn(v1 - __half2float(h1));
                    size_t o = row * (size_t)N + col;
                    *(__half2*)(Ch + o) = ph;
                    *(__half2*)(Cl + o) = pl;
                } else {
                    size_t o = row * (size_t)N + col;
                    if (EPI == 2) {
                        float2 rv = *(const float2*)(R + o);
                        v0 += rv.x; v1 += rv.y;
                    }
                    float2 ov; ov.x = v0; ov.y = v1;
                    *(float2*)(Cf + o) = ov;
                }
            }
        }
    }
}

// ---------------- junction-tree attention (QKV fused layout, fp16 split out) ------
__global__ void attn_k(const float* __restrict__ QKV, __half* __restrict__ Oh,
                       __half* __restrict__ Ol) {
    int gw = (int)((blockIdx.x * blockDim.x + threadIdx.x) >> 5);  // bl*H + h
    int lane = threadIdx.x & 31;
    int h = gw & (Hc - 1);
    int bl = gw >> 3;
    int l = bl & (Lc - 1);
    int c = l >> 2, rr = l & 3;

    int keys[8];
    int nk = 0;
    if (c > 0) {
        int p = (c - 1) << 2;
        keys[0] = p; keys[1] = p + 1; keys[2] = p + 2; keys[3] = p + 3;
        nk = 4;
    }
    int ob = c << 2;
#pragma unroll
    for (int t = 0; t < 4; t++)
        if (t <= rr) keys[nk++] = ob + t;

    int blBase = bl - l;
    size_t qoff = (size_t)bl * (3 * Dc) + h * DHc;
    float q0 = QKV[qoff + lane];
    float q1 = QKV[qoff + lane + 32];

    float s[8];
    for (int j = 0; j < nk; j++) {
        size_t ko = (size_t)(blBase + keys[j]) * (3 * Dc) + Dc + h * DHc;
        float d = q0 * QKV[ko + lane] + q1 * QKV[ko + lane + 32];
#pragma unroll
        for (int o = 16; o; o >>= 1) d += __shfl_xor_sync(0xffffffffu, d, o);
        s[j] = d * 0.125f;
    }
    float mx = s[0];
    for (int j = 1; j < nk; j++) mx = fmaxf(mx, s[j]);
    float sum = 0.f;
    for (int j = 0; j < nk; j++) { s[j] = expf(s[j] - mx); sum += s[j]; }
    float inv = 1.0f / sum;
    float o0 = 0.f, o1 = 0.f;
    for (int j = 0; j < nk; j++) {
        size_t vo = (size_t)(blBase + keys[j]) * (3 * Dc) + 2 * Dc + h * DHc;
        o0 += s[j] * QKV[vo + lane];
        o1 += s[j] * QKV[vo + lane + 32];
    }
    o0 *= inv; o1 *= inv;
    size_t oo = (size_t)bl * Dc + h * DHc + lane;
    __half h0 = __float2half_rn(o0);
    __half h1 = __float2half_rn(o1);
    Oh[oo] = h0;
    Oh[oo + 32] = h1;
    Ol[oo] = __float2half_rn(o0 - __half2float(h0));
    Ol[oo + 32] = __float2half_rn(o1 - __half2float(h1));
}

// ---------------- final projection ----------------
__global__ void out_k(const float* __restrict__ Hx, const float* __restrict__ Wt,
                      const float* __restrict__ bout, float* __restrict__ out) {
    int w = (int)((blockIdx.x * blockDim.x + threadIdx.x) >> 5);
    int lane = threadIdx.x & 31;
    if (w >= Mrows) return;
    const float* hr = Hx + (size_t)w * Dc;
    float hv[16];
#pragma unroll
    for (int t = 0; t < 16; t++) hv[t] = hr[lane + 32 * t];
    for (int n = 0; n < Ac; n++) {
        float a = 0.f;
#pragma unroll
        for (int t = 0; t < 16; t++) a += hv[t] * Wt[(lane + 32 * t) * Ac + n];
#pragma unroll
        for (int o = 16; o; o >>= 1) a += __shfl_xor_sync(0xffffffffu, a, o);
        if (lane == 0) out[(size_t)w * Ac + n] = a + bout[n];
    }
}

// ---------------- launch ----------------
extern "C" void kernel_launch(void* const* d_in, const int* in_sizes, int n_in,
                              void* d_out, int out_size) {
    const int*   x    = (const int*)d_in[0];
    const float* tok  = (const float*)d_in[2];
    const float* pos  = (const float*)d_in[3];
    const float* wq   = (const float*)d_in[4];
    const float* bq   = (const float*)d_in[5];
    const float* wk   = (const float*)d_in[6];
    const float* bk   = (const float*)d_in[7];
    const float* wv   = (const float*)d_in[8];
    const float* bv   = (const float*)d_in[9];
    const float* wo   = (const float*)d_in[10];
    const float* bo   = (const float*)d_in[11];
    const float* ln1s = (const float*)d_in[12];
    const float* ln1b = (const float*)d_in[13];
    const float* ln2s = (const float*)d_in[14];
    const float* ln2b = (const float*)d_in[15];
    const float* w1   = (const float*)d_in[16];
    const float* b1   = (const float*)d_in[17];
    const float* w2   = (const float*)d_in[18];
    const float* b2   = (const float*)d_in[19];
    const float* wout = (const float*)d_in[20];
    const float* bout = (const float*)d_in[21];
    float* outp = (float*)d_out;

    float *hb, *qkvb, *bqkvb;
    __half *nh, *nl, *fh, *fl, *wth, *wtl;
    cudaGetSymbolAddress((void**)&hb, g_h);
    cudaGetSymbolAddress((void**)&qkvb, g_qkv);
    cudaGetSymbolAddress((void**)&bqkvb, g_bqkv);
    cudaGetSymbolAddress((void**)&nh, g_nh);
    cudaGetSymbolAddress((void**)&nl, g_nl);
    cudaGetSymbolAddress((void**)&fh, g_fh);
    cudaGetSymbolAddress((void**)&fl, g_fl);
    cudaGetSymbolAddress((void**)&wth, g_wth);
    cudaGetSymbolAddress((void**)&wtl, g_wtl);

    const int SMEM = NSTG * STG_BYTES + 1024;
    static bool attr_done = false;
    if (!attr_done) {
        cudaFuncSetAttribute(gemm_hm<0>, cudaFuncAttributeMaxDynamicSharedMemorySize, SMEM);
        cudaFuncSetAttribute(gemm_hm<1>, cudaFuncAttributeMaxDynamicSharedMemorySize, SMEM);
        cudaFuncSetAttribute(gemm_hm<2>, cudaFuncAttributeMaxDynamicSharedMemorySize, SMEM);
        attr_done = true;
    }
    const int T = 256;

    // ---- weight conversion (transpose + fp16 split) ----
    {
        dim3 blk(32, 8);
        for (int l = 0; l < NLc; l++) {
            size_t qo = OFF_QKV + (size_t)l * 1536 * 512;
            wconv_k<<<dim3(16, 16), blk>>>(wq + (size_t)l * 512 * 512, wth + qo, wtl + qo, 512, 512);
            wconv_k<<<dim3(16, 16), blk>>>(wk + (size_t)l * 512 * 512, wth + qo + 512 * 512, wtl + qo + 512 * 512, 512, 512);
            wconv_k<<<dim3(16, 16), blk>>>(wv + (size_t)l * 512 * 512, wth + qo + 1024 * 512, wtl + qo + 1024 * 512, 512, 512);
            size_t oo = OFF_WO + (size_t)l * 512 * 512;
            wconv_k<<<dim3(16, 16), blk>>>(wo + (size_t)l * 512 * 512, wth + oo, wtl + oo, 512, 512);
            size_t o1 = OFF_W1 + (size_t)l * 2048 * 512;
            wconv_k<<<dim3(64, 16), blk>>>(w1 + (size_t)l * 512 * 2048, wth + o1, wtl + o1, 512, 2048);
            size_t o2 = OFF_W2 + (size_t)l * 512 * 2048;
            wconv_k<<<dim3(16, 64), blk>>>(w2 + (size_t)l * 2048 * 512, wth + o2, wtl + o2, 2048, 512);
        }
        bqkv_k<<<(NLc * 3 * Dc + T - 1) / T, T>>>(bq, bk, bv, bqkvb);
    }

    embed_k<<<(Mrows * (Dc / 4) + T - 1) / T, T>>>(x, tok, pos, hb);

    dim3 gQKV(1536 / 128, Mrows / 128);  // (12, 256)
    dim3 gD(Dc / 128, Mrows / 128);      // (4, 256)
    dim3 gFF(DFFc / 128, Mrows / 128);   // (16, 256)

    for (int l = 0; l < NLc; l++) {
        size_t qo = OFF_QKV + (size_t)l * 1536 * 512;
        size_t oo = OFF_WO + (size_t)l * 512 * 512;
        size_t o1 = OFF_W1 + (size_t)l * 2048 * 512;
        size_t o2 = OFF_W2 + (size_t)l * 512 * 2048;

        ln_hf_k<<<Mrows / 8, T>>>(hb, ln1s + l * Dc, ln1b + l * Dc, nh, nl);
        gemm_hm<0><<<gQKV, T, SMEM>>>(nh, nl, wth + qo, wtl + qo, bqkvb + l * 1536,
                                      nullptr, qkvb, nullptr, nullptr, Mrows, 1536, 512);
        attn_k<<<(Mrows * Hc) / 8, T>>>(qkvb, nh, nl);
        gemm_hm<2><<<gD, T, SMEM>>>(nh, nl, wth + oo, wtl + oo, bo + l * Dc,
                                    hb, hb, nullptr, nullptr, Mrows, 512, 512);
        ln_hf_k<<<Mrows / 8, T>>>(hb, ln2s + l * Dc, ln2b + l * Dc, nh, nl);
        gemm_hm<1><<<gFF, T, SMEM>>>(nh, nl, wth + o1, wtl + o1, b1 + l * DFFc,
                                     nullptr, nullptr, fh, fl, Mrows, 2048, 512);
        gemm_hm<2><<<gD, T, SMEM>>>(fh, fl, wth + o2, wtl + o2, b2 + l * Dc,
                                    hb, hb, nullptr, nullptr, Mrows, 512, 2048);
    }

    out_k<<<Mrows / 8, T>>>(hb, wout, bout, outp);
}

// round 5
// speedup vs baseline: 2.6902x; 1.0028x over previous
#include <cuda_runtime.h>
#include <cuda_fp16.h>
#include <math.h>
#include <stdint.h>

// Problem constants
#define Bc   32
#define Lc   1024
#define Dc   512
#define Hc   8
#define DHc  64
#define DFFc 2048
#define NLc  6
#define Ac   21
#define Mrows (Bc*Lc)   // 32768

// ---------------- PTX helpers ----------------
__device__ __forceinline__ uint32_t smem_u32(const void* p) {
    uint32_t a;
    asm("{ .reg .u64 t; cvta.to.shared.u64 t, %1; cvt.u32.u64 %0, t; }" : "=r"(a) : "l"(p));
    return a;
}
__device__ __forceinline__ void ldm_x4(uint32_t* r, uint32_t addr) {
    asm volatile("ldmatrix.sync.aligned.m8n8.x4.shared.b16 {%0,%1,%2,%3}, [%4];"
                 : "=r"(r[0]), "=r"(r[1]), "=r"(r[2]), "=r"(r[3]) : "r"(addr));
}
__device__ __forceinline__ void ldm_x2(uint32_t* r, uint32_t addr) {
    asm volatile("ldmatrix.sync.aligned.m8n8.x2.shared.b16 {%0,%1}, [%2];"
                 : "=r"(r[0]), "=r"(r[1]) : "r"(addr));
}
__device__ __forceinline__ void mma16816(float* d, const uint32_t* a, const uint32_t* b) {
    asm volatile("mma.sync.aligned.m16n8k16.row.col.f32.f16.f16.f32 "
                 "{%0,%1,%2,%3}, {%4,%5,%6,%7}, {%8,%9}, {%0,%1,%2,%3};"
                 : "+f"(d[0]), "+f"(d[1]), "+f"(d[2]), "+f"(d[3])
                 : "r"(a[0]), "r"(a[1]), "r"(a[2]), "r"(a[3]), "r"(b[0]), "r"(b[1]));
}
// fp16-accumulate variant (2 c/d regs holding 4 halves)
__device__ __forceinline__ void mma16816h(uint32_t* d, const uint32_t* a, const uint32_t* b) {
    asm volatile("mma.sync.aligned.m16n8k16.row.col.f16.f16.f16.f16 "
                 "{%0,%1}, {%2,%3,%4,%5}, {%6,%7}, {%0,%1};"
                 : "+r"(d[0]), "+r"(d[1])
                 : "r"(a[0]), "r"(a[1]), "r"(a[2]), "r"(a[3]), "r"(b[0]), "r"(b[1]));
}
#define CP_ASYNC16(dst, src) asm volatile("cp.async.cg.shared.global [%0], [%1], 16;" :: "r"(dst), "l"(src))
#define CP_COMMIT()          asm volatile("cp.async.commit_group;" ::: "memory")
#define CP_WAIT1()           asm volatile("cp.async.wait_group 1;" ::: "memory")

// ---------------- scratch ----------------
__device__ float g_h[(size_t)Mrows * Dc];          // residual fp32
__device__ float g_qkv[(size_t)Mrows * 3 * Dc];    // fused QKV fp32
__device__ __half g_nh[(size_t)Mrows * Dc];        // activation hi
__device__ __half g_nl[(size_t)Mrows * Dc];        // activation lo
__device__ __half g_fh[(size_t)Mrows * DFFc];
__device__ __half g_fl[(size_t)Mrows * DFFc];
// transposed split weights: [qkv 6*1536*512][wo 6*512*512][w1 6*2048*512][w2 6*512*2048]
#define OFF_QKV 0
#define OFF_WO  4718592
#define OFF_W1  6291456
#define OFF_W2  12582912
#define WT_TOT  18874368
__device__ __half g_wth[WT_TOT];
__device__ __half g_wtl[WT_TOT];
__device__ float g_bqkv[NLc * 3 * Dc];

// ---------------- embedding ----------------
__global__ void embed_k(const int* __restrict__ x, const float* __restrict__ tok,
                        const float* __restrict__ pos, float* __restrict__ h) {
    size_t i = (size_t)blockIdx.x * blockDim.x + threadIdx.x;
    const size_t total = (size_t)Mrows * (Dc / 4);
    if (i >= total) return;
    size_t row = i / (Dc / 4);
    int c4 = (int)(i % (Dc / 4));
    int t = x[row];
    int l = (int)(row & (Lc - 1));
    float4 a = ((const float4*)tok)[(size_t)t * (Dc / 4) + c4];
    float4 p = ((const float4*)pos)[(size_t)l * (Dc / 4) + c4];
    float4 o; o.x = a.x + p.x; o.y = a.y + p.y; o.z = a.z + p.z; o.w = a.w + p.w;
    ((float4*)h)[i] = o;
}

// ---------------- weight transpose + fp16 split (merged launches) ----------------
__device__ __forceinline__ void wconv_tile(const float* __restrict__ W,
                                           __half* __restrict__ Th, __half* __restrict__ Tl,
                                           int K, int N, int bx, int by) {
    __shared__ float t[32][33];
    int k0 = by * 32, n0 = bx * 32;
    int tx = threadIdx.x, ty = threadIdx.y;  // 32 x 8
#pragma unroll
    for (int i = 0; i < 4; i++)
        t[ty + 8 * i][tx] = W[(size_t)(k0 + ty + 8 * i) * N + n0 + tx];
    __syncthreads();
#pragma unroll
    for (int i = 0; i < 4; i++) {
        float v = t[tx][ty + 8 * i];
        __half hh = __float2half_rn(v);
        float lo = v - __half2float(hh);
        size_t o = (size_t)(n0 + ty + 8 * i) * K + k0 + tx;
        Th[o] = hh;
        Tl[o] = __float2half_rn(lo);
    }
}

// all 512x512 weights: jobs = layer*4 + {wq,wk,wv,wo}
__global__ void wconv_sq_k(const float* __restrict__ wq, const float* __restrict__ wk,
                           const float* __restrict__ wv, const float* __restrict__ wo,
                           __half* __restrict__ Th, __half* __restrict__ Tl) {
    int job = blockIdx.z;
    int l = job >> 2, w = job & 3;
    const float* src;
    size_t dst;
    if (w == 0)      { src = wq + (size_t)l * 512 * 512; dst = OFF_QKV + (size_t)l * 1536 * 512; }
    else if (w == 1) { src = wk + (size_t)l * 512 * 512; dst = OFF_QKV + (size_t)l * 1536 * 512 + 512 * 512; }
    else if (w == 2) { src = wv + (size_t)l * 512 * 512; dst = OFF_QKV + (size_t)l * 1536 * 512 + 1024 * 512; }
    else             { src = wo + (size_t)l * 512 * 512; dst = OFF_WO + (size_t)l * 512 * 512; }
    wconv_tile(src, Th + dst, Tl + dst, 512, 512, blockIdx.x, blockIdx.y);
}

// w1 (512x2048) jobs 0..5, w2 (2048x512) jobs 6..11; grid (64,16,12)
__global__ void wconv_rect_k(const float* __restrict__ w1, const float* __restrict__ w2,
                             __half* __restrict__ Th, __half* __restrict__ Tl) {
    int job = blockIdx.z;
    if (job < 6) {
        size_t dst = OFF_W1 + (size_t)job * 2048 * 512;
        wconv_tile(w1 + (size_t)job * 512 * 2048, Th + dst, Tl + dst, 512, 2048,
                   blockIdx.x, blockIdx.y);
    } else {
        int l = job - 6;
        int t = blockIdx.y * 64 + blockIdx.x;   // 0..1023
        int bx = t & 15, by = t >> 4;           // 16 x 64
        size_t dst = OFF_W2 + (size_t)l * 512 * 2048;
        wconv_tile(w2 + (size_t)l * 2048 * 512, Th + dst, Tl + dst, 2048, 512, bx, by);
    }
}

__global__ void bqkv_k(const float* __restrict__ bq, const float* __restrict__ bk,
                       const float* __restrict__ bv, float* __restrict__ o) {
    int i = blockIdx.x * blockDim.x + threadIdx.x;
    if (i >= NLc * 3 * Dc) return;
    int l = i / (3 * Dc), c = i % (3 * Dc);
    float v = (c < Dc) ? bq[l * Dc + c] : (c < 2 * Dc) ? bk[l * Dc + c - Dc] : bv[l * Dc + c - 2 * Dc];
    o[i] = v;
}

// ---------------- layernorm -> split fp16 ----------------
__global__ void ln_hf_k(const float* __restrict__ X, const float* __restrict__ gs,
                        const float* __restrict__ gb, __half* __restrict__ Yh,
                        __half* __restrict__ Yl) {
    int w = (int)((blockIdx.x * blockDim.x + threadIdx.x) >> 5);
    int lane = threadIdx.x & 31;
    if (w >= Mrows) return;
    const float* x = X + (size_t)w * Dc;
    float4 v[4];
    float s = 0.f;
#pragma unroll
    for (int t = 0; t < 4; t++) {
        v[t] = ((const float4*)x)[lane + 32 * t];
        s += v[t].x + v[t].y + v[t].z + v[t].w;
    }
#pragma unroll
    for (int o = 16; o; o >>= 1) s += __shfl_xor_sync(0xffffffffu, s, o);
    float mu = s * (1.0f / Dc);
    float ss = 0.f;
#pragma unroll
    for (int t = 0; t < 4; t++) {
        float dx = v[t].x - mu, dy = v[t].y - mu, dz = v[t].z - mu, dw = v[t].w - mu;
        ss += dx * dx + dy * dy + dz * dz + dw * dw;
    }
#pragma unroll
    for (int o = 16; o; o >>= 1) ss += __shfl_xor_sync(0xffffffffu, ss, o);
    float rs = rsqrtf(ss * (1.0f / Dc) + 1e-6f);
#pragma unroll
    for (int t = 0; t < 4; t++) {
        int f4 = lane + 32 * t;
        float4 g4 = ((const float4*)gs)[f4];
        float4 b4 = ((const float4*)gb)[f4];
        float y0 = (v[t].x - mu) * rs * g4.x + b4.x;
        float y1 = (v[t].y - mu) * rs * g4.y + b4.y;
        float y2 = (v[t].z - mu) * rs * g4.z + b4.z;
        float y3 = (v[t].w - mu) * rs * g4.w + b4.w;
        __half h0 = __float2half_rn(y0), h1 = __float2half_rn(y1);
        __half h2 = __float2half_rn(y2), h3 = __float2half_rn(y3);
        __half2 ph0; ph0.x = h0; ph0.y = h1;
        __half2 ph1; ph1.x = h2; ph1.y = h3;
        __half2 pl0;
        pl0.x = __float2half_rn(y0 - __half2float(h0));
        pl0.y = __float2half_rn(y1 - __half2float(h1));
        __half2 pl1;
        pl1.x = __float2half_rn(y2 - __half2float(h2));
        pl1.y = __float2half_rn(y3 - __half2float(h3));
        size_t base = (size_t)w * Dc + f4 * 4;
        *(__half2*)(Yh + base) = ph0;
        *(__half2*)(Yh + base + 2) = ph1;
        *(__half2*)(Yl + base) = pl0;
        *(__half2*)(Yl + base + 2) = pl1;
    }
}

// ---------------- fast accurate gelu (tanh form via expf) ----------------
__device__ __forceinline__ float gelu_fast(float x) {
    float v = x * (1.5957691216057308f + 0.07135660900000000f * x * x);
    float e = __expf(v);
    return x - __fdividef(x, e + 1.0f);
}

// ---------------- split-fp16 HMMA GEMM (cross terms in f16 accumulators) --------
// C[M,N] = A[M,K] @ B^T, B stored [N,K]. A,B given as hi/lo fp16.
// EPI 0: Cf = acc + bias;  EPI 1: Ch/Cl = split(gelu(acc+bias));  EPI 2: Cf = acc+bias+R
#define STG_BYTES 65536  // 4 tiles x 16KB
#define NSTG 3

template <int EPI>
__global__ void __launch_bounds__(256, 1) gemm_hm(
    const __half* __restrict__ Ah, const __half* __restrict__ Al,
    const __half* __restrict__ Bh, const __half* __restrict__ Bl,
    const float* __restrict__ bias, const float* __restrict__ R,
    float* __restrict__ Cf, __half* __restrict__ Ch, __half* __restrict__ Cl,
    int M, int N, int K) {
    extern __shared__ char smraw[];
    uint32_t sb = smem_u32(smraw);
    uint32_t S = (sb + 1023) & ~1023u;  // 1024-aligned smem base

    const int tid = threadIdx.x;
    const int lane = tid & 31;
    const int wid = tid >> 5;
    const int warpM = wid >> 2;   // 0..1
    const int warpN = wid & 3;    // 0..3

    const size_t mBase = (size_t)blockIdx.y * 128;
    const size_t nBase = (size_t)blockIdx.x * 128;
    const int nch = K >> 6;

    // per-thread ldmatrix offsets
    uint32_t aRow[4], bRow[4];
#pragma unroll
    for (int mt = 0; mt < 4; mt++) aRow[mt] = (warpM * 64 + mt * 16 + (lane & 15)) * 128;
#pragma unroll
    for (int nt = 0; nt < 4; nt++) bRow[nt] = (warpN * 32 + nt * 8 + (lane & 7)) * 128;
    int axor = lane >> 4;
    int bxor = (lane >> 3) & 1;
    int lsw = lane & 7;
    uint32_t aCh[4], bCh[4];
#pragma unroll
    for (int ks = 0; ks < 4; ks++) {
        aCh[ks] = (uint32_t)(((2 * ks + axor) ^ lsw) << 4);
        bCh[ks] = (uint32_t)(((2 * ks + bxor) ^ lsw) << 4);
    }

    float acc[4][4][4];      // HH term, fp32 acc
    uint32_t accx[4][4][2];  // cross terms, fp16 acc (4 halves in 2 regs)
#pragma unroll
    for (int i = 0; i < 4; i++)
#pragma unroll
        for (int j = 0; j < 4; j++) {
#pragma unroll
            for (int t = 0; t < 4; t++) acc[i][j][t] = 0.f;
            accx[i][j][0] = 0u; accx[i][j][1] = 0u;
        }

    // stage loader (cp.async): tiles 0=Ah 1=Al 2=Bh 3=Bl, 128 rows x 64 halves, swizzled
    auto load_stage = [&](int slot, int ch) {
        uint32_t sdst = S + slot * STG_BYTES;
#pragma unroll
        for (int u = 0; u < 16; u++) {
            int tile = u >> 2;
            int r = (u & 3) * 32 + (tid >> 3);
            int j = tid & 7;
            const __half* src = (tile == 0) ? Ah : (tile == 1) ? Al : (tile == 2) ? Bh : Bl;
            size_t rb = ((tile < 2) ? mBase : nBase) + r;
            const void* gsrc = src + rb * (size_t)K + (size_t)ch * 64 + j * 8;
            uint32_t d = sdst + tile * 16384 + r * 128 + (((uint32_t)(j ^ (r & 7))) << 4);
            CP_ASYNC16(d, gsrc);
        }
    };

    load_stage(0, 0); CP_COMMIT();
    load_stage(1, 1); CP_COMMIT();

    int slot = 0;
    for (int ch = 0; ch < nch; ch++) {
        CP_WAIT1();
        __syncthreads();
        int nslot = slot + 2; if (nslot >= NSTG) nslot -= NSTG;
        if (ch + 2 < nch) load_stage(nslot, ch + 2);
        CP_COMMIT();

        uint32_t base = S + slot * STG_BYTES;
#pragma unroll
        for (int ks = 0; ks < 4; ks++) {
            uint32_t ah[4][4], al[4][4], bh[4][2], bl[4][2];
#pragma unroll
            for (int mt = 0; mt < 4; mt++) ldm_x4(ah[mt], base + aRow[mt] + aCh[ks]);
#pragma unroll
            for (int nt = 0; nt < 4; nt++) ldm_x2(bh[nt], base + 32768 + bRow[nt] + bCh[ks]);
#pragma unroll
            for (int mt = 0; mt < 4; mt++) ldm_x4(al[mt], base + 16384 + aRow[mt] + aCh[ks]);
#pragma unroll
            for (int nt = 0; nt < 4; nt++) ldm_x2(bl[nt], base + 49152 + bRow[nt] + bCh[ks]);
            // HH term -> fp32 accumulators
#pragma unroll
            for (int mt = 0; mt < 4; mt++)
#pragma unroll
                for (int nt = 0; nt < 4; nt++) mma16816(acc[mt][nt], ah[mt], bh[nt]);
            // cross terms -> fp16 accumulators (partial sums ~2^-11 of main)
#pragma unroll
            for (int mt = 0; mt < 4; mt++)
#pragma unroll
                for (int nt = 0; nt < 4; nt++) mma16816h(accx[mt][nt], al[mt], bh[nt]);
#pragma unroll
            for (int mt = 0; mt < 4; mt++)
#pragma unroll
                for (int nt = 0; nt < 4; nt++) mma16816h(accx[mt][nt], ah[mt], bl[nt]);
        }
        slot++; if (slot >= NSTG) slot = 0;
    }

    // epilogue
    int r = lane >> 2;
    int cc = (lane & 3) * 2;
#pragma unroll
    for (int mt = 0; mt < 4; mt++) {
        size_t row0 = mBase + warpM * 64 + mt * 16 + r;
#pragma unroll
        for (int hf = 0; hf < 2; hf++) {
            size_t row = row0 + hf * 8;
#pragma unroll
            for (int nt = 0; nt < 4; nt++) {
                int col = (int)nBase + warpN * 32 + nt * 8 + cc;
                float2 xc = __half22float2(*reinterpret_cast<__half2*>(&accx[mt][nt][hf]));
                float v0 = acc[mt][nt][hf * 2 + 0] + xc.x + bias[col];
                float v1 = acc[mt][nt][hf * 2 + 1] + xc.y + bias[col + 1];
                if (EPI == 1) {
                    v0 = gelu_fast(v0);
                    v1 = gelu_fast(v1);
                    __half h0 = __float2half_rn(v0), h1 = __float2half_rn(v1);
                    __half2 ph; ph.x = h0; ph.y = h1;
                    __half2 pl;
                    pl.x = __float2half_rn(v0 - __half2float(h0));
                    pl.y = __float2half_rn(v1 - __half2float(h1));
                    size_t o = row * (size_t)N + col;
                    *(__half2*)(Ch + o) = ph;
                    *(__half2*)(Cl + o) = pl;
                } else {
                    size_t o = row * (size_t)N + col;
                    if (EPI == 2) {
                        float2 rv = *(const float2*)(R + o);
                        v0 += rv.x; v1 += rv.y;
                    }
                    float2 ov; ov.x = v0; ov.y = v1;
                    *(float2*)(Cf + o) = ov;
                }
            }
        }
    }
}

// ---------------- junction-tree attention (QKV fused layout, fp16 split out) ------
__global__ void attn_k(const float* __restrict__ QKV, __half* __restrict__ Oh,
                       __half* __restrict__ Ol) {
    int gw = (int)((blockIdx.x * blockDim.x + threadIdx.x) >> 5);  // bl*H + h
    int lane = threadIdx.x & 31;
    int h = gw & (Hc - 1);
    int bl = gw >> 3;
    int l = bl & (Lc - 1);
    int c = l >> 2, rr = l & 3;

    int keys[8];
    int nk = 0;
    if (c > 0) {
        int p = (c - 1) << 2;
        keys[0] = p; keys[1] = p + 1; keys[2] = p + 2; keys[3] = p + 3;
        nk = 4;
    }
    int ob = c << 2;
#pragma unroll
    for (int t = 0; t < 4; t++)
        if (t <= rr) keys[nk++] = ob + t;

    int blBase = bl - l;
    size_t qoff = (size_t)bl * (3 * Dc) + h * DHc;
    float q0 = QKV[qoff + lane];
    float q1 = QKV[qoff + lane + 32];

    float s[8];
    for (int j = 0; j < nk; j++) {
        size_t ko = (size_t)(blBase + keys[j]) * (3 * Dc) + Dc + h * DHc;
        float d = q0 * QKV[ko + lane] + q1 * QKV[ko + lane + 32];
#pragma unroll
        for (int o = 16; o; o >>= 1) d += __shfl_xor_sync(0xffffffffu, d, o);
        s[j] = d * 0.125f;
    }
    float mx = s[0];
    for (int j = 1; j < nk; j++) mx = fmaxf(mx, s[j]);
    float sum = 0.f;
    for (int j = 0; j < nk; j++) { s[j] = expf(s[j] - mx); sum += s[j]; }
    float inv = 1.0f / sum;
    float o0 = 0.f, o1 = 0.f;
    for (int j = 0; j < nk; j++) {
        size_t vo = (size_t)(blBase + keys[j]) * (3 * Dc) + 2 * Dc + h * DHc;
        o0 += s[j] * QKV[vo + lane];
        o1 += s[j] * QKV[vo + lane + 32];
    }
    o0 *= inv; o1 *= inv;
    size_t oo = (size_t)bl * Dc + h * DHc + lane;
    __half h0 = __float2half_rn(o0);
    __half h1 = __float2half_rn(o1);
    Oh[oo] = h0;
    Oh[oo + 32] = h1;
    Ol[oo] = __float2half_rn(o0 - __half2float(h0));
    Ol[oo + 32] = __float2half_rn(o1 - __half2float(h1));
}

// ---------------- final projection ----------------
__global__ void out_k(const float* __restrict__ Hx, const float* __restrict__ Wt,
                      const float* __restrict__ bout, float* __restrict__ out) {
    int w = (int)((blockIdx.x * blockDim.x + threadIdx.x) >> 5);
    int lane = threadIdx.x & 31;
    if (w >= Mrows) return;
    const float* hr = Hx + (size_t)w * Dc;
    float hv[16];
#pragma unroll
    for (int t = 0; t < 16; t++) hv[t] = hr[lane + 32 * t];
    for (int n = 0; n < Ac; n++) {
        float a = 0.f;
#pragma unroll
        for (int t = 0; t < 16; t++) a += hv[t] * Wt[(lane + 32 * t) * Ac + n];
#pragma unroll
        for (int o = 16; o; o >>= 1) a += __shfl_xor_sync(0xffffffffu, a, o);
        if (lane == 0) out[(size_t)w * Ac + n] = a + bout[n];
    }
}

// ---------------- launch ----------------
extern "C" void kernel_launch(void* const* d_in, const int* in_sizes, int n_in,
                              void* d_out, int out_size) {
    const int*   x    = (const int*)d_in[0];
    const float* tok  = (const float*)d_in[2];
    const float* pos  = (const float*)d_in[3];
    const float* wq   = (const float*)d_in[4];
    const float* bq   = (const float*)d_in[5];
    const float* wk   = (const float*)d_in[6];
    const float* bk   = (const float*)d_in[7];
    const float* wv   = (const float*)d_in[8];
    const float* bv   = (const float*)d_in[9];
    const float* wo   = (const float*)d_in[10];
    const float* bo   = (const float*)d_in[11];
    const float* ln1s = (const float*)d_in[12];
    const float* ln1b = (const float*)d_in[13];
    const float* ln2s = (const float*)d_in[14];
    const float* ln2b = (const float*)d_in[15];
    const float* w1   = (const float*)d_in[16];
    const float* b1   = (const float*)d_in[17];
    const float* w2   = (const float*)d_in[18];
    const float* b2   = (const float*)d_in[19];
    const float* wout = (const float*)d_in[20];
    const float* bout = (const float*)d_in[21];
    float* outp = (float*)d_out;

    float *hb, *qkvb, *bqkvb;
    __half *nh, *nl, *fh, *fl, *wth, *wtl;
    cudaGetSymbolAddress((void**)&hb, g_h);
    cudaGetSymbolAddress((void**)&qkvb, g_qkv);
    cudaGetSymbolAddress((void**)&bqkvb, g_bqkv);
    cudaGetSymbolAddress((void**)&nh, g_nh);
    cudaGetSymbolAddress((void**)&nl, g_nl);
    cudaGetSymbolAddress((void**)&fh, g_fh);
    cudaGetSymbolAddress((void**)&fl, g_fl);
    cudaGetSymbolAddress((void**)&wth, g_wth);
    cudaGetSymbolAddress((void**)&wtl, g_wtl);

    const int SMEM = NSTG * STG_BYTES + 1024;
    static bool attr_done = false;
    if (!attr_done) {
        cudaFuncSetAttribute(gemm_hm<0>, cudaFuncAttributeMaxDynamicSharedMemorySize, SMEM);
        cudaFuncSetAttribute(gemm_hm<1>, cudaFuncAttributeMaxDynamicSharedMemorySize, SMEM);
        cudaFuncSetAttribute(gemm_hm<2>, cudaFuncAttributeMaxDynamicSharedMemorySize, SMEM);
        attr_done = true;
    }
    const int T = 256;

    // launch order chosen so ncu (-s 5 -c 1) profiles the QKV GEMM (6th launch)
    bqkv_k<<<(NLc * 3 * Dc + T - 1) / T, T>>>(bq, bk, bv, bqkvb);                 // 1
    embed_k<<<(Mrows * (Dc / 4) + T - 1) / T, T>>>(x, tok, pos, hb);              // 2
    {
        dim3 blk(32, 8);
        wconv_sq_k<<<dim3(16, 16, 24), blk>>>(wq, wk, wv, wo, wth, wtl);          // 3
        wconv_rect_k<<<dim3(64, 16, 12), blk>>>(w1, w2, wth, wtl);                // 4
    }

    dim3 gQKV(1536 / 128, Mrows / 128);  // (12, 256)
    dim3 gD(Dc / 128, Mrows / 128);      // (4, 256)
    dim3 gFF(DFFc / 128, Mrows / 128);   // (16, 256)

    for (int l = 0; l < NLc; l++) {
        size_t qo = OFF_QKV + (size_t)l * 1536 * 512;
        size_t oo = OFF_WO + (size_t)l * 512 * 512;
        size_t o1 = OFF_W1 + (size_t)l * 2048 * 512;
        size_t o2 = OFF_W2 + (size_t)l * 512 * 2048;

        ln_hf_k<<<Mrows / 8, T>>>(hb, ln1s + l * Dc, ln1b + l * Dc, nh, nl);      // 5
        gemm_hm<0><<<gQKV, T, SMEM>>>(nh, nl, wth + qo, wtl + qo, bqkvb + l * 1536,
                                      nullptr, qkvb, nullptr, nullptr, Mrows, 1536, 512);  // 6 <- profiled
        attn_k<<<(Mrows * Hc) / 8, T>>>(qkvb, nh, nl);
        gemm_hm<2><<<gD, T, SMEM>>>(nh, nl, wth + oo, wtl + oo, bo + l * Dc,
                                    hb, hb, nullptr, nullptr, Mrows, 512, 512);
        ln_hf_k<<<Mrows / 8, T>>>(hb, ln2s + l * Dc, ln2b + l * Dc, nh, nl);
        gemm_hm<1><<<gFF, T, SMEM>>>(nh, nl, wth + o1, wtl + o1, b1 + l * DFFc,
                                     nullptr, nullptr, fh, fl, Mrows, 2048, 512);
        gemm_hm<2><<<gD, T, SMEM>>>(fh, fl, wth + o2, wtl + o2, b2 + l * Dc,
                                    hb, hb, nullptr, nullptr, Mrows, 512, 2048);
    }

    out_k<<<Mrows / 8, T>>>(hb, wout, bout, outp);
}